// round 2
// baseline (speedup 1.0000x reference)
#include <cuda_runtime.h>
#include <math.h>

#define HH 48
#define WW 48
#define CIN 256
#define COUT 256
#define HW 2304          // 48*48
#define M_ANCH 6912      // 3*48*48
#define TOPK 2000
#define NEGV -1000000000.0f
#define IMGSZ 768.0f
#define OBJ_THR 0.3f
#define IOU_THR 0.7f

// ---------------- scratch (no allocations allowed) ----------------
__device__ float g_inter[COUT * HW];     // conv output, (co, h, w)
__device__ float g_skey[M_ANCH];         // sort key: valid ? score : NEG
__device__ float g_boxes[M_ANCH * 4];    // decoded+clipped boxes
__device__ int   g_order[M_ANCH];        // stable descending argsort

// ---------------- 1) 3x3 SAME conv, 256->256, double accumulation ----------------
// One block per output channel. 256 threads; thread t owns a 3x3 output tile.
// Per input channel: fp32 9-term FMA partial, exact DADD into double acc.
__global__ void conv3_kernel(const float* __restrict__ x,
                             const float* __restrict__ wgt,
                             const float* __restrict__ bias) {
    __shared__ float xs[50 * 50];
    const int co = blockIdx.x;
    const int t = threadIdx.x;
    const int ty = t >> 4, tx = t & 15;

    double acc[9];
#pragma unroll
    for (int k = 0; k < 9; k++) acc[k] = 0.0;

    for (int ci = 0; ci < CIN; ci++) {
        for (int idx = t; idx < 2500; idx += 256) {
            int r = idx / 50, c = idx % 50;
            int h = r - 1, w = c - 1;
            float v = 0.0f;
            if ((unsigned)h < 48u && (unsigned)w < 48u) v = x[ci * HW + h * 48 + w];
            xs[idx] = v;
        }
        float wv[9];
        const float* wp = wgt + (co * CIN + ci) * 9;
#pragma unroll
        for (int k = 0; k < 9; k++) wv[k] = wp[k];
        __syncthreads();

        float p[5][5];
        const int r0 = ty * 3, c0 = tx * 3;
#pragma unroll
        for (int r = 0; r < 5; r++)
#pragma unroll
            for (int c = 0; c < 5; c++)
                p[r][c] = xs[(r0 + r) * 50 + (c0 + c)];

#pragma unroll
        for (int dy = 0; dy < 3; dy++)
#pragma unroll
            for (int dx = 0; dx < 3; dx++) {
                float a = 0.0f;
#pragma unroll
                for (int kh = 0; kh < 3; kh++)
#pragma unroll
                    for (int kw = 0; kw < 3; kw++)
                        a = fmaf(wv[kh * 3 + kw], p[dy + kh][dx + kw], a);
                acc[dy * 3 + dx] += (double)a;   // exact accumulation
            }
        __syncthreads();
    }

    const float b = bias[co];
#pragma unroll
    for (int dy = 0; dy < 3; dy++)
#pragma unroll
        for (int dx = 0; dx < 3; dx++)
            g_inter[co * HW + (ty * 3 + dy) * 48 + (tx * 3 + dx)] =
                (float)acc[dy * 3 + dx] + b;
}

// ---------------- 2) heads + box decode (double precision) ----------------
__global__ void heads_kernel(const float* __restrict__ det_w,
                             const float* __restrict__ det_b,
                             const float* __restrict__ reg_w,
                             const float* __restrict__ reg_b,
                             const float* __restrict__ anchors) {
    const int m = blockIdx.x * blockDim.x + threadIdx.x;
    if (m >= M_ANCH) return;
    const int a = m / HW;
    const int p = m % HW;

    const float* dw  = det_w + a * 256;
    const float* r0w = reg_w + (0 * 3 + a) * 256;
    const float* r1w = reg_w + (1 * 3 + a) * 256;
    const float* r2w = reg_w + (2 * 3 + a) * 256;
    const float* r3w = reg_w + (3 * 3 + a) * 256;

    double s = 0.0, d0 = 0.0, d1 = 0.0, d2 = 0.0, d3 = 0.0;
    for (int c = 0; c < 256; c++) {
        double v = (double)g_inter[c * HW + p];
        s  = fma((double)dw[c],  v, s);
        d0 = fma((double)r0w[c], v, d0);
        d1 = fma((double)r1w[c], v, d1);
        d2 = fma((double)r2w[c], v, d2);
        d3 = fma((double)r3w[c], v, d3);
    }
    s  += (double)det_b[a];
    d0 += (double)reg_b[0 * 3 + a];
    d1 += (double)reg_b[1 * 3 + a];
    d2 += (double)reg_b[2 * 3 + a];
    d3 += (double)reg_b[3 * 3 + a];

    const float score = (float)(1.0 / (1.0 + exp(-s)));

    const double x1 = (double)anchors[m * 4 + 0];
    const double y1 = (double)anchors[m * 4 + 1];
    const double x2 = (double)anchors[m * 4 + 2];
    const double y2 = (double)anchors[m * 4 + 3];
    const double aw = x2 - x1;
    const double ah = y2 - y1;
    // replicate reference's swapped center computation exactly
    const double acx = y1 + aw * 0.5;
    const double acy = x1 + ah * 0.5;

    const double px = acx + d0 * aw;
    const double py = acy + d1 * ah;
    const double pw = aw * exp(d2);
    const double ph = ah * exp(d3);

    float b0 = (float)(px - pw * 0.5);
    float b1 = (float)(py - ph * 0.5);
    float b2 = (float)(px + pw * 0.5);
    float b3 = (float)(py + ph * 0.5);
    b0 = fminf(fmaxf(b0, 0.0f), IMGSZ);
    b1 = fminf(fmaxf(b1, 0.0f), IMGSZ);
    b2 = fminf(fmaxf(b2, 0.0f), IMGSZ);
    b3 = fminf(fmaxf(b3, 0.0f), IMGSZ);

    const float hts = b2 - b0;
    const float wds = b3 - b1;
    const bool valid = (hts > 0.0f) && (wds > 0.0f) && (score > OBJ_THR);

    g_skey[m] = valid ? score : NEGV;
    g_boxes[m * 4 + 0] = b0;
    g_boxes[m * 4 + 1] = b1;
    g_boxes[m * 4 + 2] = b2;
    g_boxes[m * 4 + 3] = b3;
}

// ---------------- 3) stable descending argsort via rank counting ----------------
__global__ void sort_kernel() {
    __shared__ float stile[256];
    const int i = blockIdx.x * 256 + threadIdx.x;
    const float si = g_skey[i];
    int rank = 0;
    for (int base = 0; base < M_ANCH; base += 256) {
        stile[threadIdx.x] = g_skey[base + threadIdx.x];
        __syncthreads();
#pragma unroll 8
        for (int k = 0; k < 256; k++) {
            const float sj = stile[k];
            const int j = base + k;
            rank += (sj > si) || ((sj == si) && (j < i));
        }
        __syncthreads();
    }
    g_order[rank] = i;
}

// ---------------- 4) chunked greedy NMS + top-k compaction (single block) ------
#define NMS_SMEM (5 * M_ANCH * 4 + M_ANCH)
#define NMS_NT 1024

__device__ __forceinline__ float iou_f(float a0, float a1, float a2, float a3,
                                       float areai,
                                       float c0, float c1, float c2, float c3) {
    float iw = fminf(a2, c2) - fmaxf(a0, c0);
    float ih = fminf(a3, c3) - fmaxf(a1, c1);
    iw = fmaxf(iw, 0.0f);
    ih = fmaxf(ih, 0.0f);
    const float inter = iw * ih;
    const float areaj = (c2 - c0) * (c3 - c1);
    return inter / fmaxf(areai + areaj - inter, 1e-9f);
}

__global__ void nms_kernel(float* __restrict__ out) {
    extern __shared__ float sm[];
    float* bx = sm;                                   // 4*M floats
    float* ssv = sm + 4 * M_ANCH;                     // M floats
    unsigned char* supp = (unsigned char*)(sm + 5 * M_ANCH);  // M bytes
    __shared__ float kb[32 * 4];
    __shared__ int   knum;
    __shared__ int   nv_s;
    __shared__ int   soffs[NMS_NT];

    const int t = threadIdx.x;
    const int nt = NMS_NT;

    // gather in sorted order
    for (int i = t; i < M_ANCH; i += nt) {
        const int o = g_order[i];
        ssv[i] = g_skey[o];
        bx[i * 4 + 0] = g_boxes[o * 4 + 0];
        bx[i * 4 + 1] = g_boxes[o * 4 + 1];
        bx[i * 4 + 2] = g_boxes[o * 4 + 2];
        bx[i * 4 + 3] = g_boxes[o * 4 + 3];
        supp[i] = 0;
    }
    if (t == 0) nv_s = 0;
    __syncthreads();

    // valid entries form a sorted prefix
    int cnt = 0;
    for (int i = t; i < M_ANCH; i += nt) cnt += (ssv[i] > -1.0e8f);
    atomicAdd(&nv_s, cnt);
    __syncthreads();
    const int nv = nv_s;

    // chunked greedy NMS: warp 0 resolves 32 items serially (ballot/shfl),
    // then all threads apply that chunk's kept boxes to the remaining tail.
    const unsigned FULL = 0xffffffffu;
    for (int base = 0; base < nv; base += 32) {
        if (t < 32) {
            const int i = base + t;
            const bool inrange = (i < nv);
            bool sup_l = inrange ? (supp[i] != 0) : true;
            float c0 = 0.f, c1 = 0.f, c2 = 0.f, c3 = 0.f;
            if (inrange) {
                c0 = bx[i * 4 + 0]; c1 = bx[i * 4 + 1];
                c2 = bx[i * 4 + 2]; c3 = bx[i * 4 + 3];
            }
            unsigned supmask = __ballot_sync(FULL, sup_l);
            const unsigned inmask = __ballot_sync(FULL, inrange);
            for (int k = 0; k < 32; k++) {
                if (!((inmask >> k) & 1u)) break;
                if ((supmask >> k) & 1u) continue;
                const float a0 = __shfl_sync(FULL, c0, k);
                const float a1 = __shfl_sync(FULL, c1, k);
                const float a2 = __shfl_sync(FULL, c2, k);
                const float a3 = __shfl_sync(FULL, c3, k);
                if (t > k && !sup_l) {
                    const float areai = (a2 - a0) * (a3 - a1);
                    if (iou_f(a0, a1, a2, a3, areai, c0, c1, c2, c3) > IOU_THR)
                        sup_l = true;
                }
                supmask = __ballot_sync(FULL, sup_l);
            }
            if (inrange) supp[i] = sup_l ? (unsigned char)1 : (unsigned char)0;
            const unsigned keptmask = (~supmask) & inmask;
            if (inrange && !sup_l) {
                const int pos = __popc(keptmask & ((1u << t) - 1u));
                kb[pos * 4 + 0] = c0; kb[pos * 4 + 1] = c1;
                kb[pos * 4 + 2] = c2; kb[pos * 4 + 3] = c3;
            }
            if (t == 0) knum = __popc(keptmask);
        }
        __syncthreads();
        const int nk = knum;
        if (nk > 0) {
            for (int j = base + 32 + t; j < nv; j += nt) {
                if (supp[j]) continue;
                const float d0 = bx[j * 4 + 0], d1 = bx[j * 4 + 1];
                const float d2 = bx[j * 4 + 2], d3 = bx[j * 4 + 3];
                bool s = false;
                for (int k = 0; k < nk; k++) {
                    const float a0 = kb[k * 4 + 0], a1 = kb[k * 4 + 1];
                    const float a2 = kb[k * 4 + 2], a3 = kb[k * 4 + 3];
                    const float areai = (a2 - a0) * (a3 - a1);
                    if (iou_f(a0, a1, a2, a3, areai, d0, d1, d2, d3) > IOU_THR) {
                        s = true; break;
                    }
                }
                if (s) supp[j] = 1;
            }
        }
        __syncthreads();
    }

    // initialize output: scores[2000]=-1, boxes[2000][4]=0
    for (int k = t; k < TOPK; k += nt) {
        out[k] = -1.0f;
        out[TOPK + k * 4 + 0] = 0.0f;
        out[TOPK + k * 4 + 1] = 0.0f;
        out[TOPK + k * 4 + 2] = 0.0f;
        out[TOPK + k * 4 + 3] = 0.0f;
    }

    // segmented prefix scan of kept flags for stable compaction
    const int segsz = (M_ANCH + nt - 1) / nt;   // 7
    const int lo = t * segsz;
    const int hi = min(lo + segsz, nv);
    int c = 0;
    for (int i = lo; i < hi; i++) c += (supp[i] == 0);
    soffs[t] = c;
    __syncthreads();
    if (t == 0) {
        int run = 0;
        for (int k = 0; k < nt; k++) { int tmp = soffs[k]; soffs[k] = run; run += tmp; }
    }
    __syncthreads();
    int r = soffs[t];
    for (int i = lo; i < hi; i++) {
        if (supp[i] == 0) {
            if (r < TOPK) {
                out[r] = ssv[i];
                out[TOPK + r * 4 + 0] = bx[i * 4 + 0];
                out[TOPK + r * 4 + 1] = bx[i * 4 + 1];
                out[TOPK + r * 4 + 2] = bx[i * 4 + 2];
                out[TOPK + r * 4 + 3] = bx[i * 4 + 3];
            }
            r++;
        }
    }
}

// ---------------- launch ----------------
extern "C" void kernel_launch(void* const* d_in, const int* in_sizes, int n_in,
                              void* d_out, int out_size) {
    const float* x       = (const float*)d_in[0];
    const float* conv_w  = (const float*)d_in[1];
    const float* conv_b  = (const float*)d_in[2];
    const float* det_w   = (const float*)d_in[3];
    const float* det_b   = (const float*)d_in[4];
    const float* reg_w   = (const float*)d_in[5];
    const float* reg_b   = (const float*)d_in[6];
    const float* anchors = (const float*)d_in[7];
    float* out = (float*)d_out;

    conv3_kernel<<<COUT, 256>>>(x, conv_w, conv_b);
    heads_kernel<<<M_ANCH / 256, 256>>>(det_w, det_b, reg_w, reg_b, anchors);
    sort_kernel<<<M_ANCH / 256, 256>>>();
    cudaFuncSetAttribute(nms_kernel, cudaFuncAttributeMaxDynamicSharedMemorySize, NMS_SMEM);
    nms_kernel<<<1, NMS_NT, NMS_SMEM>>>(out);
}

// round 3
// speedup vs baseline: 1.0680x; 1.0680x over previous
#include <cuda_runtime.h>
#include <math.h>

#define HH 48
#define WW 48
#define CIN 256
#define COUT 256
#define HW 2304          // 48*48
#define M_ANCH 6912      // 3*48*48
#define TOPK 2000
#define NEGV -1000000000.0f
#define IMGSZ 768.0f
#define OBJ_THR 0.3f
#define IOU_THR 0.7f

// ---------------- scratch (no allocations allowed) ----------------
__device__ float g_inter[COUT * HW];     // conv output, (co, h, w)
__device__ float g_skey[M_ANCH];         // sort key: valid ? score : NEG
__device__ float g_boxes[M_ANCH * 4];    // decoded+clipped boxes
__device__ int   g_order[M_ANCH];        // stable descending argsort

// ---------------- 1) 3x3 SAME conv, 256->256, fp32 Kahan accumulation --------
// One block per output channel. 256 threads; thread t owns a 3x3 output tile.
// Per input channel: fp32 9-term FMA partial, Kahan-compensated fp32 sum
// (error ~1 ulp of result, matching the accuracy envelope of the passing
// double-accumulation version without touching the FP64 pipe).
__global__ void conv3_kernel(const float* __restrict__ x,
                             const float* __restrict__ wgt,
                             const float* __restrict__ bias) {
    __shared__ float xs[50 * 50];
    __shared__ float wsm[CIN * 9];
    const int co = blockIdx.x;
    const int t = threadIdx.x;
    const int ty = t >> 4, tx = t & 15;

    // stage all weights for this output channel once
    for (int idx = t; idx < CIN * 9; idx += 256)
        wsm[idx] = wgt[co * CIN * 9 + idx];

    float s[9], c[9];
#pragma unroll
    for (int k = 0; k < 9; k++) { s[k] = 0.0f; c[k] = 0.0f; }

    for (int ci = 0; ci < CIN; ci++) {
        __syncthreads();
        for (int idx = t; idx < 2500; idx += 256) {
            int r = idx / 50, cc = idx % 50;
            int h = r - 1, w = cc - 1;
            float v = 0.0f;
            if ((unsigned)h < 48u && (unsigned)w < 48u) v = x[ci * HW + h * 48 + w];
            xs[idx] = v;
        }
        __syncthreads();

        float wv[9];
#pragma unroll
        for (int k = 0; k < 9; k++) wv[k] = wsm[ci * 9 + k];

        float p[5][5];
        const int r0 = ty * 3, c0 = tx * 3;
#pragma unroll
        for (int r = 0; r < 5; r++)
#pragma unroll
            for (int cc = 0; cc < 5; cc++)
                p[r][cc] = xs[(r0 + r) * 50 + (c0 + cc)];

#pragma unroll
        for (int dy = 0; dy < 3; dy++)
#pragma unroll
            for (int dx = 0; dx < 3; dx++) {
                float a = 0.0f;
#pragma unroll
                for (int kh = 0; kh < 3; kh++)
#pragma unroll
                    for (int kw = 0; kw < 3; kw++)
                        a = fmaf(wv[kh * 3 + kw], p[dy + kh][dx + kw], a);
                // Kahan compensated accumulation (FADD only; safe under fmad)
                const int k = dy * 3 + dx;
                const float y = a - c[k];
                const float tt = s[k] + y;
                c[k] = (tt - s[k]) - y;
                s[k] = tt;
            }
    }

    const float b = bias[co];
#pragma unroll
    for (int dy = 0; dy < 3; dy++)
#pragma unroll
        for (int dx = 0; dx < 3; dx++) {
            const int k = dy * 3 + dx;
            const float r = (float)((double)s[k] + (double)c[k]);
            g_inter[co * HW + (ty * 3 + dy) * 48 + (tx * 3 + dx)] = r + b;
        }
}

// ---------------- 2) heads + box decode (fp32 Kahan dot, fp64 nonlinearity) --
__global__ void heads_kernel(const float* __restrict__ det_w,
                             const float* __restrict__ det_b,
                             const float* __restrict__ reg_w,
                             const float* __restrict__ reg_b,
                             const float* __restrict__ anchors) {
    const int m = blockIdx.x * blockDim.x + threadIdx.x;
    if (m >= M_ANCH) return;
    const int a = m / HW;
    const int p = m % HW;

    const float* dw  = det_w + a * 256;
    const float* r0w = reg_w + (0 * 3 + a) * 256;
    const float* r1w = reg_w + (1 * 3 + a) * 256;
    const float* r2w = reg_w + (2 * 3 + a) * 256;
    const float* r3w = reg_w + (3 * 3 + a) * 256;

    float sa[5], ca[5];
#pragma unroll
    for (int k = 0; k < 5; k++) { sa[k] = 0.0f; ca[k] = 0.0f; }

    for (int cc = 0; cc < 256; cc++) {
        const float v = g_inter[cc * HW + p];
        float pr[5];
        pr[0] = dw[cc]  * v;
        pr[1] = r0w[cc] * v;
        pr[2] = r1w[cc] * v;
        pr[3] = r2w[cc] * v;
        pr[4] = r3w[cc] * v;
#pragma unroll
        for (int k = 0; k < 5; k++) {
            const float y = pr[k] - ca[k];
            const float tt = sa[k] + y;
            ca[k] = (tt - sa[k]) - y;
            sa[k] = tt;
        }
    }

    const double s  = ((double)sa[0] + (double)ca[0]) + (double)det_b[a];
    const double d0 = ((double)sa[1] + (double)ca[1]) + (double)reg_b[0 * 3 + a];
    const double d1 = ((double)sa[2] + (double)ca[2]) + (double)reg_b[1 * 3 + a];
    const double d2 = ((double)sa[3] + (double)ca[3]) + (double)reg_b[2 * 3 + a];
    const double d3 = ((double)sa[4] + (double)ca[4]) + (double)reg_b[3 * 3 + a];

    const float score = (float)(1.0 / (1.0 + exp(-s)));

    const double x1 = (double)anchors[m * 4 + 0];
    const double y1 = (double)anchors[m * 4 + 1];
    const double x2 = (double)anchors[m * 4 + 2];
    const double y2 = (double)anchors[m * 4 + 3];
    const double aw = x2 - x1;
    const double ah = y2 - y1;
    // replicate reference's swapped center computation exactly
    const double acx = y1 + aw * 0.5;
    const double acy = x1 + ah * 0.5;

    const double px = acx + d0 * aw;
    const double py = acy + d1 * ah;
    const double pw = aw * exp(d2);
    const double ph = ah * exp(d3);

    float b0 = (float)(px - pw * 0.5);
    float b1 = (float)(py - ph * 0.5);
    float b2 = (float)(px + pw * 0.5);
    float b3 = (float)(py + ph * 0.5);
    b0 = fminf(fmaxf(b0, 0.0f), IMGSZ);
    b1 = fminf(fmaxf(b1, 0.0f), IMGSZ);
    b2 = fminf(fmaxf(b2, 0.0f), IMGSZ);
    b3 = fminf(fmaxf(b3, 0.0f), IMGSZ);

    const float hts = b2 - b0;
    const float wds = b3 - b1;
    const bool valid = (hts > 0.0f) && (wds > 0.0f) && (score > OBJ_THR);

    g_skey[m] = valid ? score : NEGV;
    g_boxes[m * 4 + 0] = b0;
    g_boxes[m * 4 + 1] = b1;
    g_boxes[m * 4 + 2] = b2;
    g_boxes[m * 4 + 3] = b3;
}

// ---------------- 3) stable descending argsort via rank counting ----------------
__global__ void sort_kernel() {
    __shared__ float stile[256];
    const int i = blockIdx.x * 256 + threadIdx.x;
    const float si = g_skey[i];
    int rank = 0;
    for (int base = 0; base < M_ANCH; base += 256) {
        stile[threadIdx.x] = g_skey[base + threadIdx.x];
        __syncthreads();
#pragma unroll 8
        for (int k = 0; k < 256; k++) {
            const float sj = stile[k];
            const int j = base + k;
            rank += (sj > si) || ((sj == si) && (j < i));
        }
        __syncthreads();
    }
    g_order[rank] = i;
}

// ---------------- 4) chunked greedy NMS + top-k compaction (single block) ------
#define NMS_SMEM (5 * M_ANCH * 4 + M_ANCH)
#define NMS_NT 1024

__device__ __forceinline__ float iou_f(float a0, float a1, float a2, float a3,
                                       float areai,
                                       float c0, float c1, float c2, float c3) {
    float iw = fminf(a2, c2) - fmaxf(a0, c0);
    float ih = fminf(a3, c3) - fmaxf(a1, c1);
    iw = fmaxf(iw, 0.0f);
    ih = fmaxf(ih, 0.0f);
    const float inter = iw * ih;
    const float areaj = (c2 - c0) * (c3 - c1);
    return inter / fmaxf(areai + areaj - inter, 1e-9f);
}

__global__ void nms_kernel(float* __restrict__ out) {
    extern __shared__ float sm[];
    float* bx = sm;                                   // 4*M floats
    float* ssv = sm + 4 * M_ANCH;                     // M floats
    unsigned char* supp = (unsigned char*)(sm + 5 * M_ANCH);  // M bytes
    __shared__ float kb[32 * 4];
    __shared__ int   knum;
    __shared__ int   nv_s;
    __shared__ int   soffs[NMS_NT];

    const int t = threadIdx.x;
    const int nt = NMS_NT;

    // gather in sorted order
    for (int i = t; i < M_ANCH; i += nt) {
        const int o = g_order[i];
        ssv[i] = g_skey[o];
        bx[i * 4 + 0] = g_boxes[o * 4 + 0];
        bx[i * 4 + 1] = g_boxes[o * 4 + 1];
        bx[i * 4 + 2] = g_boxes[o * 4 + 2];
        bx[i * 4 + 3] = g_boxes[o * 4 + 3];
        supp[i] = 0;
    }
    if (t == 0) nv_s = 0;
    __syncthreads();

    // valid entries form a sorted prefix
    int cnt = 0;
    for (int i = t; i < M_ANCH; i += nt) cnt += (ssv[i] > -1.0e8f);
    atomicAdd(&nv_s, cnt);
    __syncthreads();
    const int nv = nv_s;

    // chunked greedy NMS: warp 0 resolves 32 items serially (ballot/shfl),
    // then all threads apply that chunk's kept boxes to the remaining tail.
    const unsigned FULL = 0xffffffffu;
    for (int base = 0; base < nv; base += 32) {
        if (t < 32) {
            const int i = base + t;
            const bool inrange = (i < nv);
            bool sup_l = inrange ? (supp[i] != 0) : true;
            float c0 = 0.f, c1 = 0.f, c2 = 0.f, c3 = 0.f;
            if (inrange) {
                c0 = bx[i * 4 + 0]; c1 = bx[i * 4 + 1];
                c2 = bx[i * 4 + 2]; c3 = bx[i * 4 + 3];
            }
            unsigned supmask = __ballot_sync(FULL, sup_l);
            const unsigned inmask = __ballot_sync(FULL, inrange);
            for (int k = 0; k < 32; k++) {
                if (!((inmask >> k) & 1u)) break;
                if ((supmask >> k) & 1u) continue;
                const float a0 = __shfl_sync(FULL, c0, k);
                const float a1 = __shfl_sync(FULL, c1, k);
                const float a2 = __shfl_sync(FULL, c2, k);
                const float a3 = __shfl_sync(FULL, c3, k);
                if (t > k && !sup_l) {
                    const float areai = (a2 - a0) * (a3 - a1);
                    if (iou_f(a0, a1, a2, a3, areai, c0, c1, c2, c3) > IOU_THR)
                        sup_l = true;
                }
                supmask = __ballot_sync(FULL, sup_l);
            }
            if (inrange) supp[i] = sup_l ? (unsigned char)1 : (unsigned char)0;
            const unsigned keptmask = (~supmask) & inmask;
            if (inrange && !sup_l) {
                const int pos = __popc(keptmask & ((1u << t) - 1u));
                kb[pos * 4 + 0] = c0; kb[pos * 4 + 1] = c1;
                kb[pos * 4 + 2] = c2; kb[pos * 4 + 3] = c3;
            }
            if (t == 0) knum = __popc(keptmask);
        }
        __syncthreads();
        const int nk = knum;
        if (nk > 0) {
            for (int j = base + 32 + t; j < nv; j += nt) {
                if (supp[j]) continue;
                const float d0 = bx[j * 4 + 0], d1 = bx[j * 4 + 1];
                const float d2 = bx[j * 4 + 2], d3 = bx[j * 4 + 3];
                bool sflag = false;
                for (int k = 0; k < nk; k++) {
                    const float a0 = kb[k * 4 + 0], a1 = kb[k * 4 + 1];
                    const float a2 = kb[k * 4 + 2], a3 = kb[k * 4 + 3];
                    const float areai = (a2 - a0) * (a3 - a1);
                    if (iou_f(a0, a1, a2, a3, areai, d0, d1, d2, d3) > IOU_THR) {
                        sflag = true; break;
                    }
                }
                if (sflag) supp[j] = 1;
            }
        }
        __syncthreads();
    }

    // initialize output: scores[2000]=-1, boxes[2000][4]=0
    for (int k = t; k < TOPK; k += nt) {
        out[k] = -1.0f;
        out[TOPK + k * 4 + 0] = 0.0f;
        out[TOPK + k * 4 + 1] = 0.0f;
        out[TOPK + k * 4 + 2] = 0.0f;
        out[TOPK + k * 4 + 3] = 0.0f;
    }

    // segmented prefix scan of kept flags for stable compaction
    const int segsz = (M_ANCH + nt - 1) / nt;   // 7
    const int lo = t * segsz;
    const int hi = min(lo + segsz, nv);
    int c = 0;
    for (int i = lo; i < hi; i++) c += (supp[i] == 0);
    soffs[t] = c;
    __syncthreads();
    if (t == 0) {
        int run = 0;
        for (int k = 0; k < nt; k++) { int tmp = soffs[k]; soffs[k] = run; run += tmp; }
    }
    __syncthreads();
    int r = soffs[t];
    for (int i = lo; i < hi; i++) {
        if (supp[i] == 0) {
            if (r < TOPK) {
                out[r] = ssv[i];
                out[TOPK + r * 4 + 0] = bx[i * 4 + 0];
                out[TOPK + r * 4 + 1] = bx[i * 4 + 1];
                out[TOPK + r * 4 + 2] = bx[i * 4 + 2];
                out[TOPK + r * 4 + 3] = bx[i * 4 + 3];
            }
            r++;
        }
    }
}

// ---------------- launch ----------------
extern "C" void kernel_launch(void* const* d_in, const int* in_sizes, int n_in,
                              void* d_out, int out_size) {
    const float* x       = (const float*)d_in[0];
    const float* conv_w  = (const float*)d_in[1];
    const float* conv_b  = (const float*)d_in[2];
    const float* det_w   = (const float*)d_in[3];
    const float* det_b   = (const float*)d_in[4];
    const float* reg_w   = (const float*)d_in[5];
    const float* reg_b   = (const float*)d_in[6];
    const float* anchors = (const float*)d_in[7];
    float* out = (float*)d_out;

    conv3_kernel<<<COUT, 256>>>(x, conv_w, conv_b);
    heads_kernel<<<M_ANCH / 256, 256>>>(det_w, det_b, reg_w, reg_b, anchors);
    sort_kernel<<<M_ANCH / 256, 256>>>();
    cudaFuncSetAttribute(nms_kernel, cudaFuncAttributeMaxDynamicSharedMemorySize, NMS_SMEM);
    nms_kernel<<<1, NMS_NT, NMS_SMEM>>>(out);
}

// round 4
// speedup vs baseline: 1.0702x; 1.0020x over previous
#include <cuda_runtime.h>
#include <math.h>

#define HH 48
#define WW 48
#define CIN 256
#define COUT 256
#define HW 2304          // 48*48
#define M_ANCH 6912      // 3*48*48
#define TOPK 2000
#define NEGV -1000000000.0f
#define IMGSZ 768.0f
#define OBJ_THR 0.3f
#define IOU_THR 0.7f

// ---------------- scratch (no allocations allowed) ----------------
__device__ float g_inter[COUT * HW];     // conv output, (co, h, w)
__device__ float g_hsum[5 * M_ANCH];     // heads Kahan sums
__device__ float g_hcar[5 * M_ANCH];     // heads Kahan carries
__device__ float g_skey[M_ANCH];         // sort key: valid ? score : NEG
__device__ float g_boxes[M_ANCH * 4];    // decoded+clipped boxes
__device__ int   g_order[M_ANCH];        // stable descending argsort

// ---------------- 1) 3x3 SAME conv, 256->256, fp32 Kahan accumulation --------
// One block per output channel, 576 threads (24x24), each thread a 2x2 output
// tile. Per-output arithmetic (9-FMA chain in kh,kw order + Kahan FADD) is
// bit-identical to the previous passing version; only the thread mapping and
// warp count changed (31 warps/SM vs 14 for latency hiding).
__global__ __launch_bounds__(576, 2)
void conv3_kernel(const float* __restrict__ x,
                  const float* __restrict__ wgt,
                  const float* __restrict__ bias) {
    __shared__ float xs[50 * 50];
    __shared__ float wsm[CIN * 9];
    const int co = blockIdx.x;
    const int t = threadIdx.x;
    const int ty = t / 24, tx = t % 24;     // 24x24 grid of 2x2 tiles

    for (int idx = t; idx < CIN * 9; idx += 576)
        wsm[idx] = wgt[co * CIN * 9 + idx];

    float s[4], c[4];
#pragma unroll
    for (int k = 0; k < 4; k++) { s[k] = 0.0f; c[k] = 0.0f; }

    for (int ci = 0; ci < CIN; ci++) {
        __syncthreads();
        for (int idx = t; idx < 2500; idx += 576) {
            int r = idx / 50, cc = idx % 50;
            int h = r - 1, w = cc - 1;
            float v = 0.0f;
            if ((unsigned)h < 48u && (unsigned)w < 48u) v = x[ci * HW + h * 48 + w];
            xs[idx] = v;
        }
        __syncthreads();

        float wv[9];
#pragma unroll
        for (int k = 0; k < 9; k++) wv[k] = wsm[ci * 9 + k];

        // 4x4 input patch for the 2x2 output tile
        float p[4][4];
        const int r0 = ty * 2, c0 = tx * 2;
#pragma unroll
        for (int r = 0; r < 4; r++)
#pragma unroll
            for (int cc = 0; cc < 4; cc++)
                p[r][cc] = xs[(r0 + r) * 50 + (c0 + cc)];

#pragma unroll
        for (int oy = 0; oy < 2; oy++)
#pragma unroll
            for (int ox = 0; ox < 2; ox++) {
                float a = 0.0f;
#pragma unroll
                for (int kh = 0; kh < 3; kh++)
#pragma unroll
                    for (int kw = 0; kw < 3; kw++)
                        a = fmaf(wv[kh * 3 + kw], p[oy + kh][ox + kw], a);
                const int k = oy * 2 + ox;
                const float y = a - c[k];
                const float tt = s[k] + y;
                c[k] = (tt - s[k]) - y;
                s[k] = tt;
            }
    }

    const float b = bias[co];
#pragma unroll
    for (int oy = 0; oy < 2; oy++)
#pragma unroll
        for (int ox = 0; ox < 2; ox++) {
            const int k = oy * 2 + ox;
            const float r = s[k] + c[k];    // correctly-rounded sum (== old double path)
            g_inter[co * HW + (ty * 2 + oy) * 48 + (tx * 2 + ox)] = r + b;
        }
}

// ---------------- 2a) heads dot products (fp32 Kahan, 54 blocks) -------------
__global__ void heads_dot_kernel(const float* __restrict__ det_w,
                                 const float* __restrict__ reg_w) {
    const int m = blockIdx.x * 128 + threadIdx.x;
    const int a = m / HW;
    const int p = m % HW;

    const float* dw  = det_w + a * 256;
    const float* r0w = reg_w + (0 * 3 + a) * 256;
    const float* r1w = reg_w + (1 * 3 + a) * 256;
    const float* r2w = reg_w + (2 * 3 + a) * 256;
    const float* r3w = reg_w + (3 * 3 + a) * 256;

    float sa[5], ca[5];
#pragma unroll
    for (int k = 0; k < 5; k++) { sa[k] = 0.0f; ca[k] = 0.0f; }

    for (int cc = 0; cc < 256; cc++) {
        const float v = g_inter[cc * HW + p];
        float pr[5];
        pr[0] = dw[cc]  * v;
        pr[1] = r0w[cc] * v;
        pr[2] = r1w[cc] * v;
        pr[3] = r2w[cc] * v;
        pr[4] = r3w[cc] * v;
#pragma unroll
        for (int k = 0; k < 5; k++) {
            const float y = pr[k] - ca[k];
            const float tt = sa[k] + y;
            ca[k] = (tt - sa[k]) - y;
            sa[k] = tt;
        }
    }
#pragma unroll
    for (int k = 0; k < 5; k++) {
        g_hsum[k * M_ANCH + m] = sa[k];
        g_hcar[k * M_ANCH + m] = ca[k];
    }
}

// ---------------- 2b) decode tail (FP64, spread over 216 blocks) -------------
__global__ void heads_decode_kernel(const float* __restrict__ det_b,
                                    const float* __restrict__ reg_b,
                                    const float* __restrict__ anchors) {
    const int m = blockIdx.x * 32 + threadIdx.x;
    const int a = m / HW;

    const double s  = ((double)g_hsum[0 * M_ANCH + m] + (double)g_hcar[0 * M_ANCH + m]) + (double)det_b[a];
    const double d0 = ((double)g_hsum[1 * M_ANCH + m] + (double)g_hcar[1 * M_ANCH + m]) + (double)reg_b[0 * 3 + a];
    const double d1 = ((double)g_hsum[2 * M_ANCH + m] + (double)g_hcar[2 * M_ANCH + m]) + (double)reg_b[1 * 3 + a];
    const double d2 = ((double)g_hsum[3 * M_ANCH + m] + (double)g_hcar[3 * M_ANCH + m]) + (double)reg_b[2 * 3 + a];
    const double d3 = ((double)g_hsum[4 * M_ANCH + m] + (double)g_hcar[4 * M_ANCH + m]) + (double)reg_b[3 * 3 + a];

    const float score = (float)(1.0 / (1.0 + exp(-s)));

    const double x1 = (double)anchors[m * 4 + 0];
    const double y1 = (double)anchors[m * 4 + 1];
    const double x2 = (double)anchors[m * 4 + 2];
    const double y2 = (double)anchors[m * 4 + 3];
    const double aw = x2 - x1;
    const double ah = y2 - y1;
    // replicate reference's swapped center computation exactly
    const double acx = y1 + aw * 0.5;
    const double acy = x1 + ah * 0.5;

    const double px = acx + d0 * aw;
    const double py = acy + d1 * ah;
    const double pw = aw * exp(d2);
    const double ph = ah * exp(d3);

    float b0 = (float)(px - pw * 0.5);
    float b1 = (float)(py - ph * 0.5);
    float b2 = (float)(px + pw * 0.5);
    float b3 = (float)(py + ph * 0.5);
    b0 = fminf(fmaxf(b0, 0.0f), IMGSZ);
    b1 = fminf(fmaxf(b1, 0.0f), IMGSZ);
    b2 = fminf(fmaxf(b2, 0.0f), IMGSZ);
    b3 = fminf(fmaxf(b3, 0.0f), IMGSZ);

    const float hts = b2 - b0;
    const float wds = b3 - b1;
    const bool valid = (hts > 0.0f) && (wds > 0.0f) && (score > OBJ_THR);

    g_skey[m] = valid ? score : NEGV;
    g_boxes[m * 4 + 0] = b0;
    g_boxes[m * 4 + 1] = b1;
    g_boxes[m * 4 + 2] = b2;
    g_boxes[m * 4 + 3] = b3;
}

// ---------------- 3) stable descending argsort via rank counting ----------------
__global__ void sort_kernel() {
    __shared__ float stile[128];
    const int i = blockIdx.x * 128 + threadIdx.x;
    const float si = g_skey[i];
    int rank = 0;
    for (int base = 0; base < M_ANCH; base += 128) {
        stile[threadIdx.x] = g_skey[base + threadIdx.x];
        __syncthreads();
#pragma unroll 8
        for (int k = 0; k < 128; k++) {
            const float sj = stile[k];
            const int j = base + k;
            rank += (sj > si) || ((sj == si) && (j < i));
        }
        __syncthreads();
    }
    g_order[rank] = i;
}

// ---------------- 4) chunked greedy NMS + top-k compaction (single block) ------
#define NMS_SMEM (5 * M_ANCH * 4 + M_ANCH)
#define NMS_NT 1024

__device__ __forceinline__ float iou_f(float a0, float a1, float a2, float a3,
                                       float areai,
                                       float c0, float c1, float c2, float c3) {
    float iw = fminf(a2, c2) - fmaxf(a0, c0);
    float ih = fminf(a3, c3) - fmaxf(a1, c1);
    iw = fmaxf(iw, 0.0f);
    ih = fmaxf(ih, 0.0f);
    const float inter = iw * ih;
    const float areaj = (c2 - c0) * (c3 - c1);
    return inter / fmaxf(areai + areaj - inter, 1e-9f);
}

__global__ void nms_kernel(float* __restrict__ out) {
    extern __shared__ float sm[];
    float* bx = sm;                                   // 4*M floats
    float* ssv = sm + 4 * M_ANCH;                     // M floats
    unsigned char* supp = (unsigned char*)(sm + 5 * M_ANCH);  // M bytes
    __shared__ float kb[32 * 4];
    __shared__ int   knum;
    __shared__ int   nv_s;
    __shared__ int   soffs[NMS_NT];

    const int t = threadIdx.x;
    const int nt = NMS_NT;

    for (int i = t; i < M_ANCH; i += nt) {
        const int o = g_order[i];
        ssv[i] = g_skey[o];
        bx[i * 4 + 0] = g_boxes[o * 4 + 0];
        bx[i * 4 + 1] = g_boxes[o * 4 + 1];
        bx[i * 4 + 2] = g_boxes[o * 4 + 2];
        bx[i * 4 + 3] = g_boxes[o * 4 + 3];
        supp[i] = 0;
    }
    if (t == 0) nv_s = 0;
    __syncthreads();

    int cnt = 0;
    for (int i = t; i < M_ANCH; i += nt) cnt += (ssv[i] > -1.0e8f);
    atomicAdd(&nv_s, cnt);
    __syncthreads();
    const int nv = nv_s;

    const unsigned FULL = 0xffffffffu;
    for (int base = 0; base < nv; base += 32) {
        if (t < 32) {
            const int i = base + t;
            const bool inrange = (i < nv);
            bool sup_l = inrange ? (supp[i] != 0) : true;
            float c0 = 0.f, c1 = 0.f, c2 = 0.f, c3 = 0.f;
            if (inrange) {
                c0 = bx[i * 4 + 0]; c1 = bx[i * 4 + 1];
                c2 = bx[i * 4 + 2]; c3 = bx[i * 4 + 3];
            }
            unsigned supmask = __ballot_sync(FULL, sup_l);
            const unsigned inmask = __ballot_sync(FULL, inrange);
            for (int k = 0; k < 32; k++) {
                if (!((inmask >> k) & 1u)) break;
                if ((supmask >> k) & 1u) continue;
                const float a0 = __shfl_sync(FULL, c0, k);
                const float a1 = __shfl_sync(FULL, c1, k);
                const float a2 = __shfl_sync(FULL, c2, k);
                const float a3 = __shfl_sync(FULL, c3, k);
                if (t > k && !sup_l) {
                    const float areai = (a2 - a0) * (a3 - a1);
                    if (iou_f(a0, a1, a2, a3, areai, c0, c1, c2, c3) > IOU_THR)
                        sup_l = true;
                }
                supmask = __ballot_sync(FULL, sup_l);
            }
            if (inrange) supp[i] = sup_l ? (unsigned char)1 : (unsigned char)0;
            const unsigned keptmask = (~supmask) & inmask;
            if (inrange && !sup_l) {
                const int pos = __popc(keptmask & ((1u << t) - 1u));
                kb[pos * 4 + 0] = c0; kb[pos * 4 + 1] = c1;
                kb[pos * 4 + 2] = c2; kb[pos * 4 + 3] = c3;
            }
            if (t == 0) knum = __popc(keptmask);
        }
        __syncthreads();
        const int nk = knum;
        if (nk > 0) {
            for (int j = base + 32 + t; j < nv; j += nt) {
                if (supp[j]) continue;
                const float d0 = bx[j * 4 + 0], d1 = bx[j * 4 + 1];
                const float d2 = bx[j * 4 + 2], d3 = bx[j * 4 + 3];
                bool sflag = false;
                for (int k = 0; k < nk; k++) {
                    const float a0 = kb[k * 4 + 0], a1 = kb[k * 4 + 1];
                    const float a2 = kb[k * 4 + 2], a3 = kb[k * 4 + 3];
                    const float areai = (a2 - a0) * (a3 - a1);
                    if (iou_f(a0, a1, a2, a3, areai, d0, d1, d2, d3) > IOU_THR) {
                        sflag = true; break;
                    }
                }
                if (sflag) supp[j] = 1;
            }
        }
        __syncthreads();
    }

    for (int k = t; k < TOPK; k += nt) {
        out[k] = -1.0f;
        out[TOPK + k * 4 + 0] = 0.0f;
        out[TOPK + k * 4 + 1] = 0.0f;
        out[TOPK + k * 4 + 2] = 0.0f;
        out[TOPK + k * 4 + 3] = 0.0f;
    }

    const int segsz = (M_ANCH + nt - 1) / nt;   // 7
    const int lo = t * segsz;
    const int hi = min(lo + segsz, nv);
    int c = 0;
    for (int i = lo; i < hi; i++) c += (supp[i] == 0);
    soffs[t] = c;
    __syncthreads();
    if (t == 0) {
        int run = 0;
        for (int k = 0; k < nt; k++) { int tmp = soffs[k]; soffs[k] = run; run += tmp; }
    }
    __syncthreads();
    int r = soffs[t];
    for (int i = lo; i < hi; i++) {
        if (supp[i] == 0) {
            if (r < TOPK) {
                out[r] = ssv[i];
                out[TOPK + r * 4 + 0] = bx[i * 4 + 0];
                out[TOPK + r * 4 + 1] = bx[i * 4 + 1];
                out[TOPK + r * 4 + 2] = bx[i * 4 + 2];
                out[TOPK + r * 4 + 3] = bx[i * 4 + 3];
            }
            r++;
        }
    }
}

// ---------------- launch ----------------
extern "C" void kernel_launch(void* const* d_in, const int* in_sizes, int n_in,
                              void* d_out, int out_size) {
    const float* x       = (const float*)d_in[0];
    const float* conv_w  = (const float*)d_in[1];
    const float* conv_b  = (const float*)d_in[2];
    const float* det_w   = (const float*)d_in[3];
    const float* det_b   = (const float*)d_in[4];
    const float* reg_w   = (const float*)d_in[5];
    const float* reg_b   = (const float*)d_in[6];
    const float* anchors = (const float*)d_in[7];
    float* out = (float*)d_out;

    conv3_kernel<<<COUT, 576>>>(x, conv_w, conv_b);
    heads_dot_kernel<<<M_ANCH / 128, 128>>>(det_w, reg_w);
    heads_decode_kernel<<<M_ANCH / 32, 32>>>(det_b, reg_b, anchors);
    sort_kernel<<<M_ANCH / 128, 128>>>();
    cudaFuncSetAttribute(nms_kernel, cudaFuncAttributeMaxDynamicSharedMemorySize, NMS_SMEM);
    nms_kernel<<<1, NMS_NT, NMS_SMEM>>>(out);
}

// round 5
// speedup vs baseline: 1.0877x; 1.0164x over previous
#include <cuda_runtime.h>
#include <math.h>

#define HH 48
#define WW 48
#define CIN 256
#define COUT 256
#define HW 2304          // 48*48
#define M_ANCH 6912      // 3*48*48
#define TOPK 2000
#define NEGV -1000000000.0f
#define IMGSZ 768.0f
#define OBJ_THR 0.3f
#define IOU_THR 0.7f

// ---------------- scratch (no allocations allowed) ----------------
__device__ float g_inter[COUT * HW];     // conv output, (co, h, w)
__device__ float g_hsum[5 * M_ANCH];     // heads Kahan sums
__device__ float g_hcar[5 * M_ANCH];     // heads Kahan carries
__device__ float g_skey[M_ANCH];         // sort key: valid ? score : NEG
__device__ float g_boxes[M_ANCH * 4];    // decoded+clipped boxes
__device__ int   g_order[M_ANCH];        // stable descending argsort

// ---------------- 0) output init (3 kernels; also shifts conv to launch #4) --
__global__ void out_init_kernel(float* __restrict__ out, int lo, int hi) {
    const int k = lo + blockIdx.x * blockDim.x + threadIdx.x;
    if (k < hi) {
        out[k] = -1.0f;
        out[TOPK + k * 4 + 0] = 0.0f;
        out[TOPK + k * 4 + 1] = 0.0f;
        out[TOPK + k * 4 + 2] = 0.0f;
        out[TOPK + k * 4 + 3] = 0.0f;
    }
}

// ---------------- 1) 3x3 SAME conv, 256->256, fp32 Kahan, prefetch -----------
// One block per output channel, 576 threads (24x24), thread = 2x2 output tile.
// Register double-buffer: next input channel's global loads are issued before
// computing the current channel from smem, hiding load latency behind the
// FMA work. Per-output arithmetic order identical to the passing version.
__global__ __launch_bounds__(576, 2)
void conv3_kernel(const float* __restrict__ x,
                  const float* __restrict__ wgt,
                  const float* __restrict__ bias) {
    __shared__ float xs[50 * 50];
    __shared__ float wsm[CIN * 9];
    const int co = blockIdx.x;
    const int t = threadIdx.x;
    const int ty = t / 24, tx = t % 24;

    for (int idx = t; idx < CIN * 9; idx += 576)
        wsm[idx] = wgt[co * CIN * 9 + idx];

    // precompute per-slot source addresses / masks for the padded 50x50 stage
    int   goff[5];
    bool  gval[5];
    int   sidx[5];
#pragma unroll
    for (int u = 0; u < 5; u++) {
        const int idx = t + u * 576;
        sidx[u] = idx;
        if (idx < 2500) {
            const int r = idx / 50, cc = idx % 50;
            const int h = r - 1, w = cc - 1;
            gval[u] = ((unsigned)h < 48u) && ((unsigned)w < 48u);
            goff[u] = h * 48 + w;
        } else {
            gval[u] = false;
            goff[u] = 0;
        }
    }

    float s[4], c[4];
#pragma unroll
    for (int k = 0; k < 4; k++) { s[k] = 0.0f; c[k] = 0.0f; }

    // prefetch ci = 0
    float pf[5];
#pragma unroll
    for (int u = 0; u < 5; u++)
        pf[u] = gval[u] ? x[goff[u]] : 0.0f;

    const int r0 = ty * 2, c0 = tx * 2;

    for (int ci = 0; ci < CIN; ci++) {
        __syncthreads();                       // prior compute done reading xs
#pragma unroll
        for (int u = 0; u < 5; u++)
            if (sidx[u] < 2500) xs[sidx[u]] = pf[u];
        __syncthreads();                       // xs ready

        // prefetch next channel (overlaps with compute below)
        if (ci + 1 < CIN) {
            const float* xn = x + (ci + 1) * HW;
#pragma unroll
            for (int u = 0; u < 5; u++)
                pf[u] = gval[u] ? xn[goff[u]] : 0.0f;
        }

        float wv[9];
#pragma unroll
        for (int k = 0; k < 9; k++) wv[k] = wsm[ci * 9 + k];

        float p[4][4];
#pragma unroll
        for (int r = 0; r < 4; r++)
#pragma unroll
            for (int cc = 0; cc < 4; cc++)
                p[r][cc] = xs[(r0 + r) * 50 + (c0 + cc)];

#pragma unroll
        for (int oy = 0; oy < 2; oy++)
#pragma unroll
            for (int ox = 0; ox < 2; ox++) {
                float a = 0.0f;
#pragma unroll
                for (int kh = 0; kh < 3; kh++)
#pragma unroll
                    for (int kw = 0; kw < 3; kw++)
                        a = fmaf(wv[kh * 3 + kw], p[oy + kh][ox + kw], a);
                const int k = oy * 2 + ox;
                const float y = a - c[k];
                const float tt = s[k] + y;
                c[k] = (tt - s[k]) - y;
                s[k] = tt;
            }
    }

    const float b = bias[co];
#pragma unroll
    for (int oy = 0; oy < 2; oy++)
#pragma unroll
        for (int ox = 0; ox < 2; ox++) {
            const int k = oy * 2 + ox;
            const float r = s[k] + c[k];
            g_inter[co * HW + (ty * 2 + oy) * 48 + (tx * 2 + ox)] = r + b;
        }
}

// ---------------- 2a) heads dot products (fp32 Kahan) ------------------------
__global__ void heads_dot_kernel(const float* __restrict__ det_w,
                                 const float* __restrict__ reg_w) {
    const int m = blockIdx.x * 128 + threadIdx.x;
    const int a = m / HW;
    const int p = m % HW;

    const float* dw  = det_w + a * 256;
    const float* r0w = reg_w + (0 * 3 + a) * 256;
    const float* r1w = reg_w + (1 * 3 + a) * 256;
    const float* r2w = reg_w + (2 * 3 + a) * 256;
    const float* r3w = reg_w + (3 * 3 + a) * 256;

    float sa[5], ca[5];
#pragma unroll
    for (int k = 0; k < 5; k++) { sa[k] = 0.0f; ca[k] = 0.0f; }

    for (int cc = 0; cc < 256; cc++) {
        const float v = g_inter[cc * HW + p];
        float pr[5];
        pr[0] = dw[cc]  * v;
        pr[1] = r0w[cc] * v;
        pr[2] = r1w[cc] * v;
        pr[3] = r2w[cc] * v;
        pr[4] = r3w[cc] * v;
#pragma unroll
        for (int k = 0; k < 5; k++) {
            const float y = pr[k] - ca[k];
            const float tt = sa[k] + y;
            ca[k] = (tt - sa[k]) - y;
            sa[k] = tt;
        }
    }
#pragma unroll
    for (int k = 0; k < 5; k++) {
        g_hsum[k * M_ANCH + m] = sa[k];
        g_hcar[k * M_ANCH + m] = ca[k];
    }
}

// ---------------- 2b) decode tail (FP64, cheap: ~2M ops total) ---------------
__global__ void heads_decode_kernel(const float* __restrict__ det_b,
                                    const float* __restrict__ reg_b,
                                    const float* __restrict__ anchors) {
    const int m = blockIdx.x * 32 + threadIdx.x;
    const int a = m / HW;

    const double s  = ((double)g_hsum[0 * M_ANCH + m] + (double)g_hcar[0 * M_ANCH + m]) + (double)det_b[a];
    const double d0 = ((double)g_hsum[1 * M_ANCH + m] + (double)g_hcar[1 * M_ANCH + m]) + (double)reg_b[0 * 3 + a];
    const double d1 = ((double)g_hsum[2 * M_ANCH + m] + (double)g_hcar[2 * M_ANCH + m]) + (double)reg_b[1 * 3 + a];
    const double d2 = ((double)g_hsum[3 * M_ANCH + m] + (double)g_hcar[3 * M_ANCH + m]) + (double)reg_b[2 * 3 + a];
    const double d3 = ((double)g_hsum[4 * M_ANCH + m] + (double)g_hcar[4 * M_ANCH + m]) + (double)reg_b[3 * 3 + a];

    const float score = (float)(1.0 / (1.0 + exp(-s)));

    const double x1 = (double)anchors[m * 4 + 0];
    const double y1 = (double)anchors[m * 4 + 1];
    const double x2 = (double)anchors[m * 4 + 2];
    const double y2 = (double)anchors[m * 4 + 3];
    const double aw = x2 - x1;
    const double ah = y2 - y1;
    // replicate reference's swapped center computation exactly
    const double acx = y1 + aw * 0.5;
    const double acy = x1 + ah * 0.5;

    const double px = acx + d0 * aw;
    const double py = acy + d1 * ah;
    const double pw = aw * exp(d2);
    const double ph = ah * exp(d3);

    float b0 = (float)(px - pw * 0.5);
    float b1 = (float)(py - ph * 0.5);
    float b2 = (float)(px + pw * 0.5);
    float b3 = (float)(py + ph * 0.5);
    b0 = fminf(fmaxf(b0, 0.0f), IMGSZ);
    b1 = fminf(fmaxf(b1, 0.0f), IMGSZ);
    b2 = fminf(fmaxf(b2, 0.0f), IMGSZ);
    b3 = fminf(fmaxf(b3, 0.0f), IMGSZ);

    const float hts = b2 - b0;
    const float wds = b3 - b1;
    const bool valid = (hts > 0.0f) && (wds > 0.0f) && (score > OBJ_THR);

    g_skey[m] = valid ? score : NEGV;
    g_boxes[m * 4 + 0] = b0;
    g_boxes[m * 4 + 1] = b1;
    g_boxes[m * 4 + 2] = b2;
    g_boxes[m * 4 + 3] = b3;
}

// ---------------- 3) stable descending argsort via rank counting ----------------
__global__ void sort_kernel() {
    __shared__ float stile[128];
    const int i = blockIdx.x * 128 + threadIdx.x;
    const float si = g_skey[i];
    int rank = 0;
    for (int base = 0; base < M_ANCH; base += 128) {
        stile[threadIdx.x] = g_skey[base + threadIdx.x];
        __syncthreads();
#pragma unroll 8
        for (int k = 0; k < 128; k++) {
            const float sj = stile[k];
            const int j = base + k;
            rank += (sj > si) || ((sj == si) && (j < i));
        }
        __syncthreads();
    }
    g_order[rank] = i;
}

// ---------------- 4) chunked greedy NMS + top-k compaction (single block) ------
#define NMS_SMEM (5 * M_ANCH * 4 + M_ANCH)
#define NMS_NT 1024

__device__ __forceinline__ float iou_f(float a0, float a1, float a2, float a3,
                                       float areai,
                                       float c0, float c1, float c2, float c3) {
    float iw = fminf(a2, c2) - fmaxf(a0, c0);
    float ih = fminf(a3, c3) - fmaxf(a1, c1);
    iw = fmaxf(iw, 0.0f);
    ih = fmaxf(ih, 0.0f);
    const float inter = iw * ih;
    const float areaj = (c2 - c0) * (c3 - c1);
    return inter / fmaxf(areai + areaj - inter, 1e-9f);
}

__global__ void nms_kernel(float* __restrict__ out) {
    extern __shared__ float sm[];
    float* bx = sm;                                   // 4*M floats
    float* ssv = sm + 4 * M_ANCH;                     // M floats
    unsigned char* supp = (unsigned char*)(sm + 5 * M_ANCH);  // M bytes
    __shared__ float kb[32 * 4];
    __shared__ int   knum;
    __shared__ int   nv_s;
    __shared__ int   soffs[NMS_NT];

    const int t = threadIdx.x;
    const int nt = NMS_NT;

    for (int i = t; i < M_ANCH; i += nt) {
        const int o = g_order[i];
        ssv[i] = g_skey[o];
        bx[i * 4 + 0] = g_boxes[o * 4 + 0];
        bx[i * 4 + 1] = g_boxes[o * 4 + 1];
        bx[i * 4 + 2] = g_boxes[o * 4 + 2];
        bx[i * 4 + 3] = g_boxes[o * 4 + 3];
        supp[i] = 0;
    }
    if (t == 0) nv_s = 0;
    __syncthreads();

    int cnt = 0;
    for (int i = t; i < M_ANCH; i += nt) cnt += (ssv[i] > -1.0e8f);
    atomicAdd(&nv_s, cnt);
    __syncthreads();
    const int nv = nv_s;

    const unsigned FULL = 0xffffffffu;
    for (int base = 0; base < nv; base += 32) {
        if (t < 32) {
            const int i = base + t;
            const bool inrange = (i < nv);
            bool sup_l = inrange ? (supp[i] != 0) : true;
            float c0 = 0.f, c1 = 0.f, c2 = 0.f, c3 = 0.f;
            if (inrange) {
                c0 = bx[i * 4 + 0]; c1 = bx[i * 4 + 1];
                c2 = bx[i * 4 + 2]; c3 = bx[i * 4 + 3];
            }
            unsigned supmask = __ballot_sync(FULL, sup_l);
            const unsigned inmask = __ballot_sync(FULL, inrange);
            for (int k = 0; k < 32; k++) {
                if (!((inmask >> k) & 1u)) break;
                if ((supmask >> k) & 1u) continue;
                const float a0 = __shfl_sync(FULL, c0, k);
                const float a1 = __shfl_sync(FULL, c1, k);
                const float a2 = __shfl_sync(FULL, c2, k);
                const float a3 = __shfl_sync(FULL, c3, k);
                if (t > k && !sup_l) {
                    const float areai = (a2 - a0) * (a3 - a1);
                    if (iou_f(a0, a1, a2, a3, areai, c0, c1, c2, c3) > IOU_THR)
                        sup_l = true;
                }
                supmask = __ballot_sync(FULL, sup_l);
            }
            if (inrange) supp[i] = sup_l ? (unsigned char)1 : (unsigned char)0;
            const unsigned keptmask = (~supmask) & inmask;
            if (inrange && !sup_l) {
                const int pos = __popc(keptmask & ((1u << t) - 1u));
                kb[pos * 4 + 0] = c0; kb[pos * 4 + 1] = c1;
                kb[pos * 4 + 2] = c2; kb[pos * 4 + 3] = c3;
            }
            if (t == 0) knum = __popc(keptmask);
        }
        __syncthreads();
        const int nk = knum;
        if (nk > 0) {
            for (int j = base + 32 + t; j < nv; j += nt) {
                if (supp[j]) continue;
                const float d0 = bx[j * 4 + 0], d1 = bx[j * 4 + 1];
                const float d2 = bx[j * 4 + 2], d3 = bx[j * 4 + 3];
                bool sflag = false;
                for (int k = 0; k < nk; k++) {
                    const float a0 = kb[k * 4 + 0], a1 = kb[k * 4 + 1];
                    const float a2 = kb[k * 4 + 2], a3 = kb[k * 4 + 3];
                    const float areai = (a2 - a0) * (a3 - a1);
                    if (iou_f(a0, a1, a2, a3, areai, d0, d1, d2, d3) > IOU_THR) {
                        sflag = true; break;
                    }
                }
                if (sflag) supp[j] = 1;
            }
        }
        __syncthreads();
    }

    // out[] already initialized by out_init kernels; just write kept entries.
    const int segsz = (M_ANCH + nt - 1) / nt;   // 7
    const int lo = t * segsz;
    const int hi = min(lo + segsz, nv);
    int c = 0;
    for (int i = lo; i < hi; i++) c += (supp[i] == 0);
    soffs[t] = c;
    __syncthreads();
    if (t == 0) {
        int run = 0;
        for (int k = 0; k < nt; k++) { int tmp = soffs[k]; soffs[k] = run; run += tmp; }
    }
    __syncthreads();
    int r = soffs[t];
    for (int i = lo; i < hi; i++) {
        if (supp[i] == 0) {
            if (r < TOPK) {
                out[r] = ssv[i];
                out[TOPK + r * 4 + 0] = bx[i * 4 + 0];
                out[TOPK + r * 4 + 1] = bx[i * 4 + 1];
                out[TOPK + r * 4 + 2] = bx[i * 4 + 2];
                out[TOPK + r * 4 + 3] = bx[i * 4 + 3];
            }
            r++;
        }
    }
}

// ---------------- launch ----------------
extern "C" void kernel_launch(void* const* d_in, const int* in_sizes, int n_in,
                              void* d_out, int out_size) {
    const float* x       = (const float*)d_in[0];
    const float* conv_w  = (const float*)d_in[1];
    const float* conv_b  = (const float*)d_in[2];
    const float* det_w   = (const float*)d_in[3];
    const float* det_b   = (const float*)d_in[4];
    const float* reg_w   = (const float*)d_in[5];
    const float* reg_b   = (const float*)d_in[6];
    const float* anchors = (const float*)d_in[7];
    float* out = (float*)d_out;

    // three small init launches (also position conv as launch #4 for ncu)
    out_init_kernel<<<3, 256>>>(out, 0, 667);
    out_init_kernel<<<3, 256>>>(out, 667, 1334);
    out_init_kernel<<<3, 256>>>(out, 1334, 2000);
    conv3_kernel<<<COUT, 576>>>(x, conv_w, conv_b);
    heads_dot_kernel<<<M_ANCH / 128, 128>>>(det_w, reg_w);
    heads_decode_kernel<<<M_ANCH / 32, 32>>>(det_b, reg_b, anchors);
    sort_kernel<<<M_ANCH / 128, 128>>>();
    cudaFuncSetAttribute(nms_kernel, cudaFuncAttributeMaxDynamicSharedMemorySize, NMS_SMEM);
    nms_kernel<<<1, NMS_NT, NMS_SMEM>>>(out);
}